// round 11
// baseline (speedup 1.0000x reference)
#include <cuda_runtime.h>
#include <math.h>

#define B_TOT   512
#define T_STEPS 2000
#define N_INP   32
#define N_HID   200
#define N_OUT   3
#define KDIM    (N_INP + N_HID)
#define NB      4
#define NCTA    (B_TOT / NB)
#define NTHR    256
#define VTH     1.0f

// dynamic SMEM layout (bytes)
#define OFF_WRT   0
#define WRT_BYTES (N_HID * N_HID * 4)        // 160000: WrT[j][n] transposed recurrent weights
#define OFF_XS    (OFF_WRT + WRT_BYTES)
#define XS_BYTES  (4 * N_INP * NB * 4)       // 2048: 4-slot ring x[t&3][i] as float4 over batches
#define OFF_SUM   (OFF_XS + XS_BYTES)
#define SUM_BYTES (3 * 4 * 4)                // rotating summary[3 phases][4 batches]
#define OFF_MSK   (OFF_SUM + SUM_BYTES)
#define MSK_BYTES (3 * 7 * 4 * 4)            // rotating masks[3][7 warps][4 batches]
#define SMEM_BYTES (OFF_MSK + MSK_BYTES + 16)

__device__ __forceinline__ float sigm(float v) { return 1.0f / (1.0f + expf(-v)); }

__device__ __forceinline__ unsigned long long pack_dup(float w) {
    unsigned long long r;
    asm("mov.b64 %0, {%1, %1};" : "=l"(r) : "f"(w));
    return r;
}
__device__ __forceinline__ void fma_x2(unsigned long long& acc,
                                       unsigned long long a, unsigned long long b) {
    asm("fma.rn.f32x2 %0, %1, %2, %3;" : "=l"(acc) : "l"(a), "l"(b), "l"(acc));
}
__device__ __forceinline__ void unpack2(unsigned long long v, float& lo, float& hi) {
    asm("mov.b64 {%0, %1}, %2;" : "=f"(lo), "=f"(hi) : "l"(v));
}

extern __shared__ char smch[];

#define XG(bl, T) __ldg(xbase + (size_t)(bl) * (T_STEPS * N_INP) + (size_t)(T) * N_INP)

__global__ void __launch_bounds__(NTHR, 1)
snn_sparse_kernel(const float* __restrict__ x,
                  const float* __restrict__ W1,
                  const float* __restrict__ b1,
                  const float* __restrict__ tau_n,
                  const float* __restrict__ tau_m1,
                  const float* __restrict__ W2,
                  const float* __restrict__ b2,
                  const float* __restrict__ tau_m2,
                  const float* __restrict__ mask,
                  float* __restrict__ out)
{
    float*    WrT  = (float*)(smch + OFF_WRT);      // [200][200]
    float4*   xs4  = (float4*)(smch + OFF_XS);      // [4][32]
    unsigned* summ = (unsigned*)(smch + OFF_SUM);   // [3][4]
    unsigned* msk  = (unsigned*)(smch + OFF_MSK);   // [3][7][4]

    const int tid  = threadIdx.x;
    const int wid  = tid >> 5;
    const int lane = tid & 31;
    const int b0   = blockIdx.x * NB;

    // stage transposed recurrent weights (cols 32..231 of W1*mask)
    for (int idx = tid; idx < N_HID * N_HID; idx += NTHR) {
        int nn = idx / N_HID;
        int j  = idx - nn * N_HID;
        WrT[j * N_HID + nn] = W1[nn * KDIM + N_INP + j] * mask[nn * KDIM + N_INP + j];
    }
    if (tid < 12) summ[tid] = 0;

    const int  n       = tid;
    const bool active  = (n < N_HID);
    const bool is_comp = (wid < 7);

    float beta = 0.f, omb = 0.f, a1 = 0.f, oma1 = 0.f;
    unsigned long long wpk[N_INP];
    unsigned long long b1pk = 0ull;
    if (active) {
        beta = sigm(tau_n[n]);   omb  = 1.0f - beta;
        a1   = sigm(tau_m1[n]);  oma1 = 1.0f - a1;
        b1pk = pack_dup(b1[n]);
#pragma unroll
        for (int i = 0; i < N_INP; ++i)
            wpk[i] = pack_dup(W1[n * KDIM + i] * mask[n * KDIM + i]);
    } else {
#pragma unroll
        for (int i = 0; i < N_INP; ++i) wpk[i] = 0ull;
    }
    float a2v[N_OUT];
#pragma unroll
    for (int o = 0; o < N_OUT; ++o) a2v[o] = sigm(tau_m2[o]);

    float mem1[NB] = {0.f,0.f,0.f,0.f};
    float din [NB] = {0.f,0.f,0.f,0.f};
    float spk [NB] = {0.f,0.f,0.f,0.f};
    float Us  [NB] = {0.f,0.f,0.f,0.f};
    float spk0[NB] = {0.f,0.f,0.f,0.f};
    float Wac[N_OUT][NB];
#pragma unroll
    for (int o = 0; o < N_OUT; ++o)
#pragma unroll
        for (int b = 0; b < NB; ++b) Wac[o][b] = 0.f;
    float hs = 0.f;

    // warp 7: x staging prologue (slots 0,1 in smem; t=2,3 in regs)
    const float* xbase = x + (size_t)b0 * (T_STEPS * N_INP) + lane;
    float4 rC = make_float4(0.f,0.f,0.f,0.f), rD = rC;
    if (wid == 7) {
        float4 A, Bv;
        A.x  = XG(0,0); A.y  = XG(1,0); A.z  = XG(2,0); A.w  = XG(3,0);
        Bv.x = XG(0,1); Bv.y = XG(1,1); Bv.z = XG(2,1); Bv.w = XG(3,1);
        rC.x = XG(0,2); rC.y = XG(1,2); rC.z = XG(2,2); rC.w = XG(3,2);
        rD.x = XG(0,3); rD.y = XG(1,3); rD.z = XG(2,3); rD.w = XG(3,3);
        xs4[0 * N_INP + lane] = A;
        xs4[1 * N_INP + lane] = Bv;
    }
    __syncthreads();

    int pw = 0;  // write phase = t%3
#pragma unroll 1
    for (int t = 0; t < T_STEPS; ++t) {
        int pz = pw + 1; if (pz == 3) pz = 0;  // zero phase = (t+1)%3
        int pr = pz + 1; if (pr == 3) pr = 0;  // read phase = (t-1)%3

        if (is_comp) {
            // dense input projection: weights in regs, x broadcast from ring
            unsigned long long acc01 = b1pk, acc23 = b1pk;
            const ulonglong2* xv = (const ulonglong2*)(xs4 + (t & 3) * N_INP);
#pragma unroll
            for (int i = 0; i < N_INP; ++i) {
                ulonglong2 kv = xv[i];
                fma_x2(acc01, wpk[i], kv.x);
                fma_x2(acc23, wpk[i], kv.y);
            }
            float cur[NB];
            unpack2(acc01, cur[0], cur[1]);
            unpack2(acc23, cur[2], cur[3]);

            // event-driven recurrent input (steady state: 1 broadcast load + test)
            uint4 sv = *(const uint4*)(summ + pr * 4);
            if (sv.x | sv.y | sv.z | sv.w) {
#pragma unroll
                for (int b = 0; b < NB; ++b) {
                    unsigned sb = (b == 0) ? sv.x : (b == 1) ? sv.y : (b == 2) ? sv.z : sv.w;
                    if (sb) {
#pragma unroll 1
                        for (int w = 0; w < 7; ++w) {
                            unsigned m = msk[(pr * 7 + w) * 4 + b];
                            while (m) {
                                int j = (w << 5) + __ffs(m) - 1;
                                m &= m - 1;
                                if (active) cur[b] += WrT[j * N_HID + n];
                            }
                        }
                    }
                }
            }

            // neuron state update
            float sstep = 0.f;
#pragma unroll
            for (int b = 0; b < NB; ++b) {
                din[b]  = fmaf(beta, din[b], omb * cur[b]);
                mem1[b] = fmaf(a1, mem1[b], oma1 * din[b]) - spk[b];
                spk[b]  = (mem1[b] > VTH) ? 1.0f : 0.0f;
                sstep  += spk[b];
            }

            // publish spikes as bitmasks + summary
            unsigned bal0 = __ballot_sync(0xffffffffu, spk[0] > 0.f);
            unsigned bal1 = __ballot_sync(0xffffffffu, spk[1] > 0.f);
            unsigned bal2 = __ballot_sync(0xffffffffu, spk[2] > 0.f);
            unsigned bal3 = __ballot_sync(0xffffffffu, spk[3] > 0.f);
            if (lane < 4) {
                unsigned mw = (lane == 0) ? bal0 : (lane == 1) ? bal1
                            : (lane == 2) ? bal2 : bal3;
                msk[(pw * 7 + wid) * 4 + lane] = mw;
                if (mw) atomicOr(&summ[pw * 4 + lane], mw);
            }
            if (tid < 4) summ[pz * 4 + tid] = 0;

            // readout bookkeeping, gated behind sticky spike flag
            hs += sstep;
            if (hs > 0.f) {
                if (t == 0) {
#pragma unroll
                    for (int b = 0; b < NB; ++b) spk0[b] = spk[b];
                } else {
#pragma unroll
                    for (int b = 0; b < NB; ++b) Us[b] += spk[b];
                }
#pragma unroll
                for (int o = 0; o < N_OUT; ++o)
#pragma unroll
                    for (int b = 0; b < NB; ++b)
                        Wac[o][b] = fmaf(a2v[o], Wac[o][b], spk[b]);
            }
        } else {
            // warp 7: stage x(t+2), prefetch x(t+4)
            int tp2 = t + 2, tp4 = t + 4;
            if ((t & 1) == 0) {
                if (tp2 < T_STEPS) xs4[(tp2 & 3) * N_INP + lane] = rC;
                if (tp4 < T_STEPS) {
                    rC.x = XG(0,tp4); rC.y = XG(1,tp4);
                    rC.z = XG(2,tp4); rC.w = XG(3,tp4);
                }
            } else {
                if (tp2 < T_STEPS) xs4[(tp2 & 3) * N_INP + lane] = rD;
                if (tp4 < T_STEPS) {
                    rD.x = XG(0,tp4); rD.y = XG(1,tp4);
                    rD.z = XG(2,tp4); rD.w = XG(3,tp4);
                }
            }
        }
        __syncthreads();
        pw = pz;
    }

    // epilogue: out[b][o] = (sum_n W2[o,n]*A_o[n,b] + b2[o]*S_c[o]) / T
    float* red = (float*)smch;  // reuse WrT region: [12][N_HID]
    if (active) {
#pragma unroll
        for (int o = 0; o < N_OUT; ++o)
#pragma unroll
            for (int b = 0; b < NB; ++b)
                red[(o * NB + b) * N_HID + n] = Us[b] + a2v[o] * (spk0[b] - Wac[o][b]);
    }
    __syncthreads();

    if (tid < N_OUT * NB) {
        const int o = tid / NB;
        const int b = tid % NB;
        const float* Arow = red + tid * N_HID;
        const float* w2r  = W2 + o * N_HID;
        float s = 0.f;
#pragma unroll 8
        for (int j = 0; j < N_HID; ++j) s = fmaf(__ldg(w2r + j), Arow[j], s);

        const float a   = a2v[o];
        const float aT  = powf(a, (float)T_STEPS);
        const float amT = a - aT;
        const float Sc  = amT + (float)(T_STEPS - 1) - amT / (1.0f - a);

        out[(size_t)(b0 + b) * N_OUT + o] = (s + __ldg(b2 + o) * Sc) * (1.0f / (float)T_STEPS);
    }
}

extern "C" void kernel_launch(void* const* d_in, const int* in_sizes, int n_in,
                              void* d_out, int out_size) {
    const float* x      = (const float*)d_in[0];
    const float* W1     = (const float*)d_in[1];
    const float* b1     = (const float*)d_in[2];
    const float* tau_n  = (const float*)d_in[3];
    const float* tau_m1 = (const float*)d_in[4];
    const float* W2     = (const float*)d_in[5];
    const float* b2     = (const float*)d_in[6];
    const float* tau_m2 = (const float*)d_in[7];
    const float* mask   = (const float*)d_in[8];
    float*       out    = (float*)d_out;

    cudaFuncSetAttribute(snn_sparse_kernel,
                         cudaFuncAttributeMaxDynamicSharedMemorySize, SMEM_BYTES);

    snn_sparse_kernel<<<NCTA, NTHR, SMEM_BYTES>>>(
        x, W1, b1, tau_n, tau_m1, W2, b2, tau_m2, mask, out);
}

// round 12
// speedup vs baseline: 1.0599x; 1.0599x over previous
#include <cuda_runtime.h>
#include <math.h>

#define B_TOT   512
#define T_STEPS 2000
#define N_INP   32
#define N_HID   200
#define N_OUT   3
#define KDIM    (N_INP + N_HID)
#define NB      4
#define NCTA    (B_TOT / NB)
#define NTHR    256
#define VTH     1.0f

// per-CTA "did any of my 4 batches ever spike" flags (phase1 -> phase2)
__device__ unsigned g_flags[NCTA];

__device__ __forceinline__ float sigm(float v) { return 1.0f / (1.0f + expf(-v)); }

__device__ __forceinline__ unsigned long long pack_dup(float w) {
    unsigned long long r;
    asm("mov.b64 %0, {%1, %1};" : "=l"(r) : "f"(w));
    return r;
}
__device__ __forceinline__ void unpack2(unsigned long long v, float& lo, float& hi) {
    asm("mov.b64 {%0, %1}, %2;" : "=f"(lo), "=f"(hi) : "l"(v));
}
__device__ __forceinline__ unsigned long long fma_x2(unsigned long long a,
                                                     unsigned long long b,
                                                     unsigned long long c) {
    unsigned long long d;
    asm("fma.rn.f32x2 %0, %1, %2, %3;" : "=l"(d) : "l"(a), "l"(b), "l"(c));
    return d;
}
__device__ __forceinline__ unsigned long long mul_x2(unsigned long long a,
                                                     unsigned long long b) {
    unsigned long long d;
    asm("mul.rn.f32x2 %0, %1, %2;" : "=l"(d) : "l"(a), "l"(b));
    return d;
}
__device__ __forceinline__ unsigned long long add_x2(unsigned long long a,
                                                     unsigned long long b) {
    unsigned long long d;
    asm("add.rn.f32x2 %0, %1, %2;" : "=l"(d) : "l"(a), "l"(b));
    return d;
}

#define XG(bl, T) __ldg(xbase + (size_t)(bl) * (T_STEPS * N_INP) + (size_t)(T) * N_INP)

// ============================================================================
// Phase 1: zero-spike assumption, no inter-thread communication.
// Exact up to the first would-be spike -> max(mem1) > VTH is a sound detector.
// ============================================================================
__global__ void __launch_bounds__(NTHR, 1)
snn_detect_kernel(const float* __restrict__ x,
                  const float* __restrict__ W1,
                  const float* __restrict__ b1,
                  const float* __restrict__ tau_n,
                  const float* __restrict__ tau_m1,
                  const float* __restrict__ mask)
{
    __shared__ float4 xs4[4 * N_INP];   // 4-slot ring: x[t&3][i] packed over 4 batches

    const int tid  = threadIdx.x;
    const int wid  = tid >> 5;
    const int lane = tid & 31;
    const int b0   = blockIdx.x * NB;

    if (tid == 0) g_flags[blockIdx.x] = 0;

    const bool active = (tid < N_HID);
    unsigned long long wpk[N_INP];
    unsigned long long b1pk = 0ull, beta2 = 0ull, omb2 = 0ull, a12 = 0ull, oma12 = 0ull;
    if (active) {
        float beta = sigm(tau_n[tid]);
        float a1   = sigm(tau_m1[tid]);
        beta2 = pack_dup(beta);  omb2  = pack_dup(1.0f - beta);
        a12   = pack_dup(a1);    oma12 = pack_dup(1.0f - a1);
        b1pk  = pack_dup(b1[tid]);
#pragma unroll
        for (int i = 0; i < N_INP; ++i)
            wpk[i] = pack_dup(W1[tid * KDIM + i] * mask[tid * KDIM + i]);
    } else {
#pragma unroll
        for (int i = 0; i < N_INP; ++i) wpk[i] = 0ull;
    }

    // warp 7: x staging (slots 0,1 in smem; t=2,3 held in regs)
    const float* xbase = x + (size_t)b0 * (T_STEPS * N_INP) + lane;
    float4 rC = make_float4(0.f, 0.f, 0.f, 0.f), rD = rC;
    if (wid == 7) {
        float4 A, Bv;
        A.x  = XG(0,0); A.y  = XG(1,0); A.z  = XG(2,0); A.w  = XG(3,0);
        Bv.x = XG(0,1); Bv.y = XG(1,1); Bv.z = XG(2,1); Bv.w = XG(3,1);
        rC.x = XG(0,2); rC.y = XG(1,2); rC.z = XG(2,2); rC.w = XG(3,2);
        rD.x = XG(0,3); rD.y = XG(1,3); rD.z = XG(2,3); rD.w = XG(3,3);
        xs4[0 * N_INP + lane] = A;
        xs4[1 * N_INP + lane] = Bv;
    }
    __syncthreads();

    unsigned long long din01 = 0ull, din23 = 0ull, mem01 = 0ull, mem23 = 0ull;
    float mmax = 0.0f;

#pragma unroll 1
    for (int t = 0; t < T_STEPS; ++t) {
        if (wid < 7) {
            const ulonglong2* xv = (const ulonglong2*)(xs4 + (t & 3) * N_INP);
            // split accumulator chains (16 deep) to halve dependent latency
            unsigned long long a01 = b1pk, a23 = b1pk, c01 = 0ull, c23 = 0ull;
#pragma unroll
            for (int i = 0; i < 16; ++i) {
                ulonglong2 kv = xv[i];
                a01 = fma_x2(wpk[i], kv.x, a01);
                a23 = fma_x2(wpk[i], kv.y, a23);
            }
#pragma unroll
            for (int i = 16; i < 32; ++i) {
                ulonglong2 kv = xv[i];
                c01 = fma_x2(wpk[i], kv.x, c01);
                c23 = fma_x2(wpk[i], kv.y, c23);
            }
            unsigned long long cur01 = add_x2(a01, c01);
            unsigned long long cur23 = add_x2(a23, c23);

            // packed leak filters (spikes pinned to 0: no soft-reset term)
            din01 = fma_x2(beta2, din01, mul_x2(omb2, cur01));
            din23 = fma_x2(beta2, din23, mul_x2(omb2, cur23));
            mem01 = fma_x2(a12, mem01, mul_x2(oma12, din01));
            mem23 = fma_x2(a12, mem23, mul_x2(oma12, din23));

            float m0, m1, m2, m3;
            unpack2(mem01, m0, m1);
            unpack2(mem23, m2, m3);
            mmax = fmaxf(mmax, fmaxf(fmaxf(m0, m1), fmaxf(m2, m3)));
        } else {
            // warp 7: stage x(t+2) into ring slot, prefetch x(t+4)
            int tp2 = t + 2, tp4 = t + 4;
            if ((t & 1) == 0) {
                if (tp2 < T_STEPS) xs4[(tp2 & 3) * N_INP + lane] = rC;
                if (tp4 < T_STEPS) {
                    rC.x = XG(0,tp4); rC.y = XG(1,tp4);
                    rC.z = XG(2,tp4); rC.w = XG(3,tp4);
                }
            } else {
                if (tp2 < T_STEPS) xs4[(tp2 & 3) * N_INP + lane] = rD;
                if (tp4 < T_STEPS) {
                    rD.x = XG(0,tp4); rD.y = XG(1,tp4);
                    rD.z = XG(2,tp4); rD.w = XG(3,tp4);
                }
            }
        }
        __syncthreads();
    }

    unsigned bal = __ballot_sync(0xffffffffu, mmax > VTH);
    if (lane == 0 && bal) atomicOr(&g_flags[blockIdx.x], 1u);
}

// ============================================================================
// Phase 2: flag==0 -> closed-form output (bit-identical to zero-spike epilogue).
// flag!=0 -> full exact synchronized recurrence (R11 logic, recurrent weights
// read from global; correctness fallback, expected never to run).
// ============================================================================
__global__ void __launch_bounds__(NTHR, 1)
snn_solve_kernel(const float* __restrict__ x,
                 const float* __restrict__ W1,
                 const float* __restrict__ b1,
                 const float* __restrict__ tau_n,
                 const float* __restrict__ tau_m1,
                 const float* __restrict__ W2,
                 const float* __restrict__ b2,
                 const float* __restrict__ tau_m2,
                 const float* __restrict__ mask,
                 float* __restrict__ out)
{
    __shared__ float4   xs4[4 * N_INP];
    __shared__ unsigned summ[3 * 4];
    __shared__ unsigned msk[3 * 7 * 4];
    __shared__ float    red[N_OUT * NB * N_HID];

    const int tid  = threadIdx.x;
    const int wid  = tid >> 5;
    const int lane = tid & 31;
    const int b0   = blockIdx.x * NB;

    float a2v[N_OUT];
#pragma unroll
    for (int o = 0; o < N_OUT; ++o) a2v[o] = sigm(tau_m2[o]);

    if (g_flags[blockIdx.x] == 0u) {
        // zero spikes: s == 0 exactly -> out = b2[o] * Sc / T (bit-identical)
        if (tid < N_OUT * NB) {
            const int o = tid / NB;
            const int b = tid % NB;
            const float a   = a2v[o];
            const float aT  = powf(a, (float)T_STEPS);
            const float amT = a - aT;
            const float Sc  = amT + (float)(T_STEPS - 1) - amT / (1.0f - a);
            out[(size_t)(b0 + b) * N_OUT + o] = (0.0f + b2[o] * Sc) * (1.0f / (float)T_STEPS);
        }
        return;
    }

    // ---------------- exact fallback (never expected to execute) -------------
    if (tid < 12) summ[tid] = 0;

    const int  n       = tid;
    const bool active  = (n < N_HID);
    const bool is_comp = (wid < 7);

    float beta = 0.f, omb = 0.f, a1 = 0.f, oma1 = 0.f;
    unsigned long long wpk[N_INP];
    unsigned long long b1pk = 0ull;
    if (active) {
        beta = sigm(tau_n[n]);   omb  = 1.0f - beta;
        a1   = sigm(tau_m1[n]);  oma1 = 1.0f - a1;
        b1pk = pack_dup(b1[n]);
#pragma unroll
        for (int i = 0; i < N_INP; ++i)
            wpk[i] = pack_dup(W1[n * KDIM + i] * mask[n * KDIM + i]);
    } else {
#pragma unroll
        for (int i = 0; i < N_INP; ++i) wpk[i] = 0ull;
    }

    float mem1[NB] = {0.f,0.f,0.f,0.f};
    float din [NB] = {0.f,0.f,0.f,0.f};
    float spk [NB] = {0.f,0.f,0.f,0.f};
    float Us  [NB] = {0.f,0.f,0.f,0.f};
    float spk0[NB] = {0.f,0.f,0.f,0.f};
    float Wac[N_OUT][NB];
#pragma unroll
    for (int o = 0; o < N_OUT; ++o)
#pragma unroll
        for (int b = 0; b < NB; ++b) Wac[o][b] = 0.f;

    const float* xbase = x + (size_t)b0 * (T_STEPS * N_INP) + lane;
    float4 rC = make_float4(0.f,0.f,0.f,0.f), rD = rC;
    if (wid == 7) {
        float4 A, Bv;
        A.x  = XG(0,0); A.y  = XG(1,0); A.z  = XG(2,0); A.w  = XG(3,0);
        Bv.x = XG(0,1); Bv.y = XG(1,1); Bv.z = XG(2,1); Bv.w = XG(3,1);
        rC.x = XG(0,2); rC.y = XG(1,2); rC.z = XG(2,2); rC.w = XG(3,2);
        rD.x = XG(0,3); rD.y = XG(1,3); rD.z = XG(2,3); rD.w = XG(3,3);
        xs4[0 * N_INP + lane] = A;
        xs4[1 * N_INP + lane] = Bv;
    }
    __syncthreads();

    int pw = 0;
#pragma unroll 1
    for (int t = 0; t < T_STEPS; ++t) {
        int pz = pw + 1; if (pz == 3) pz = 0;
        int pr = pz + 1; if (pr == 3) pr = 0;

        if (is_comp) {
            unsigned long long acc01 = b1pk, acc23 = b1pk;
            const ulonglong2* xv = (const ulonglong2*)(xs4 + (t & 3) * N_INP);
#pragma unroll
            for (int i = 0; i < N_INP; ++i) {
                ulonglong2 kv = xv[i];
                acc01 = fma_x2(wpk[i], kv.x, acc01);
                acc23 = fma_x2(wpk[i], kv.y, acc23);
            }
            float cur[NB];
            unpack2(acc01, cur[0], cur[1]);
            unpack2(acc23, cur[2], cur[3]);

            uint4 sv = *(const uint4*)(summ + pr * 4);
            if (sv.x | sv.y | sv.z | sv.w) {
#pragma unroll
                for (int b = 0; b < NB; ++b) {
                    unsigned sb = (b == 0) ? sv.x : (b == 1) ? sv.y : (b == 2) ? sv.z : sv.w;
                    if (sb) {
#pragma unroll 1
                        for (int w = 0; w < 7; ++w) {
                            unsigned m = msk[(pr * 7 + w) * 4 + b];
                            while (m) {
                                int j = (w << 5) + __ffs(m) - 1;
                                m &= m - 1;
                                if (active)
                                    cur[b] += W1[n * KDIM + N_INP + j] *
                                              mask[n * KDIM + N_INP + j];
                            }
                        }
                    }
                }
            }

#pragma unroll
            for (int b = 0; b < NB; ++b) {
                din[b]  = fmaf(beta, din[b], omb * cur[b]);
                mem1[b] = fmaf(a1, mem1[b], oma1 * din[b]) - spk[b];
                spk[b]  = (mem1[b] > VTH) ? 1.0f : 0.0f;
            }

            unsigned bal0 = __ballot_sync(0xffffffffu, spk[0] > 0.f);
            unsigned bal1 = __ballot_sync(0xffffffffu, spk[1] > 0.f);
            unsigned bal2 = __ballot_sync(0xffffffffu, spk[2] > 0.f);
            unsigned bal3 = __ballot_sync(0xffffffffu, spk[3] > 0.f);
            if (lane < 4) {
                unsigned mw = (lane == 0) ? bal0 : (lane == 1) ? bal1
                            : (lane == 2) ? bal2 : bal3;
                msk[(pw * 7 + wid) * 4 + lane] = mw;
                if (mw) atomicOr(&summ[pw * 4 + lane], mw);
            }
            if (tid < 4) summ[pz * 4 + tid] = 0;

            if (t == 0) {
#pragma unroll
                for (int b = 0; b < NB; ++b) spk0[b] = spk[b];
            } else {
#pragma unroll
                for (int b = 0; b < NB; ++b) Us[b] += spk[b];
            }
#pragma unroll
            for (int o = 0; o < N_OUT; ++o)
#pragma unroll
                for (int b = 0; b < NB; ++b)
                    Wac[o][b] = fmaf(a2v[o], Wac[o][b], spk[b]);
        } else {
            int tp2 = t + 2, tp4 = t + 4;
            if ((t & 1) == 0) {
                if (tp2 < T_STEPS) xs4[(tp2 & 3) * N_INP + lane] = rC;
                if (tp4 < T_STEPS) {
                    rC.x = XG(0,tp4); rC.y = XG(1,tp4);
                    rC.z = XG(2,tp4); rC.w = XG(3,tp4);
                }
            } else {
                if (tp2 < T_STEPS) xs4[(tp2 & 3) * N_INP + lane] = rD;
                if (tp4 < T_STEPS) {
                    rD.x = XG(0,tp4); rD.y = XG(1,tp4);
                    rD.z = XG(2,tp4); rD.w = XG(3,tp4);
                }
            }
        }
        __syncthreads();
        pw = pz;
    }

    if (active) {
#pragma unroll
        for (int o = 0; o < N_OUT; ++o)
#pragma unroll
            for (int b = 0; b < NB; ++b)
                red[(o * NB + b) * N_HID + n] = Us[b] + a2v[o] * (spk0[b] - Wac[o][b]);
    }
    __syncthreads();

    if (tid < N_OUT * NB) {
        const int o = tid / NB;
        const int b = tid % NB;
        const float* Arow = red + tid * N_HID;
        const float* w2r  = W2 + o * N_HID;
        float s = 0.f;
#pragma unroll 8
        for (int j = 0; j < N_HID; ++j) s = fmaf(__ldg(w2r + j), Arow[j], s);

        const float a   = a2v[o];
        const float aT  = powf(a, (float)T_STEPS);
        const float amT = a - aT;
        const float Sc  = amT + (float)(T_STEPS - 1) - amT / (1.0f - a);

        out[(size_t)(b0 + b) * N_OUT + o] = (s + b2[o] * Sc) * (1.0f / (float)T_STEPS);
    }
}

extern "C" void kernel_launch(void* const* d_in, const int* in_sizes, int n_in,
                              void* d_out, int out_size) {
    const float* x      = (const float*)d_in[0];
    const float* W1     = (const float*)d_in[1];
    const float* b1     = (const float*)d_in[2];
    const float* tau_n  = (const float*)d_in[3];
    const float* tau_m1 = (const float*)d_in[4];
    const float* W2     = (const float*)d_in[5];
    const float* b2     = (const float*)d_in[6];
    const float* tau_m2 = (const float*)d_in[7];
    const float* mask   = (const float*)d_in[8];
    float*       out    = (float*)d_out;

    snn_detect_kernel<<<NCTA, NTHR>>>(x, W1, b1, tau_n, tau_m1, mask);
    snn_solve_kernel<<<NCTA, NTHR>>>(x, W1, b1, tau_n, tau_m1, W2, b2, tau_m2, mask, out);
}